// round 15
// baseline (speedup 1.0000x reference)
#include <cuda_runtime.h>

typedef unsigned long long u64;

#define THREADS 256
#define GRID    2048

// ---- smem (bytes) ----
#define WBUF_B   18688          // paired o-rows: w(o,p) = (o>>1)*292 + (o&1)*144 + p (floats)
#define SLAB_OFF 18688          // slab: 192 rows (c*48 + ck) x 36 floats
#define SLAB_B   27648
#define MB_OFF   (SLAB_OFF + SLAB_B)    // 46336
#define SMEM_B   (MB_OFF + 16)          // 46352 -> 4 CTAs/SM

// 16MB staging: scratch[loc][s], s = oh*512 + j*32 + bg*8 + og*2 + pair
//   j = jp*4 + m;  b = bg*8 + jp*2 + pair;  o = oh*16 + og*4 + m
__device__ float g_scratch[4096 * 1024];

__device__ __forceinline__ void fma2(u64& d, u64 a, u64 b) {
    asm("fma.rn.f32x2 %0, %1, %2, %0;" : "+l"(d) : "l"(a), "l"(b));
}
__device__ __forceinline__ u64 add2(u64 a, u64 b) {
    u64 r; asm("add.rn.f32x2 %0, %1, %2;" : "=l"(r) : "l"(a), "l"(b)); return r;
}
__device__ __forceinline__ u64 pack2(float v) {
    u64 r; asm("mov.b64 %0, {%1, %1};" : "=l"(r) : "f"(v)); return r;
}
__device__ __forceinline__ void unpackf2(u64 d, float& lo, float& hi) {
    asm("mov.b64 {%0, %1}, %2;" : "=f"(lo), "=f"(hi) : "l"(d));
}
__device__ __forceinline__ unsigned smem_u32(const void* p) {
    unsigned a;
    asm("{ .reg .u64 t; cvta.to.shared.u64 t, %1; cvt.u32.u64 %0, t; }" : "=r"(a) : "l"(p));
    return a;
}

__global__ __launch_bounds__(THREADS, 4) void xonv_main(
    const float* __restrict__ x,        // (32, 16, 64, 64)
    const float* __restrict__ weights,  // (64, 64, 32, 16, 3, 3)
    const float* __restrict__ bias)     // (64, 64, 32)
{
    extern __shared__ __align__(16) char sm[];
    float* wsf   = (float*)sm;
    float* slabf = (float*)(sm + SLAB_OFF);
    const unsigned smbase = smem_u32(sm);
    const unsigned mb = smbase + MB_OFF;

    const int tid  = threadIdx.x;
    const int lane = tid & 31;
    const int wid  = tid >> 5;
    const int h    = blockIdx.x >> 5;
    const int w0   = (blockIdx.x & 31) * 2;
    const int loc0 = h * 64 + w0;

    if (tid == 0)
        asm volatile("mbarrier.init.shared.b64 [%0], %1;" :: "r"(mb), "r"(32) : "memory");
    __syncthreads();

    // -------- DMA weights for loc0 --------
    if (tid < 32) {
        asm volatile("mbarrier.arrive.expect_tx.shared.b64 _, [%0], %1;"
                     :: "r"(mb), "r"(576) : "memory");
        const char* src = (const char*)weights + ((size_t)loc0 * 32 + tid) * 576;
        unsigned dst = smbase + (tid >> 1) * 1168 + (tid & 1) * 576;
        asm volatile("cp.async.bulk.shared::cta.global.mbarrier::complete_tx::bytes "
                     "[%0], [%1], %2, [%3];"
                     :: "r"(dst), "l"(src), "r"(576), "r"(mb) : "memory");
    }

    // -------- stage x slab: row = c*48 + ck, 36-float stride --------
    {
        const int dr = lane >> 2;
        const int c  = lane & 3;
        const int ww = w0 + c - 1;
        const bool wok = (unsigned)ww < 64u;
        #pragma unroll
        for (int itb = 0; itb < 4; ++itb) {
            const int b = itb * 8 + wid;
            const float* xb = x + (size_t)b * 65536;
            #pragma unroll
            for (int itc = 0; itc < 6; ++itc) {
                int ck = itc * 8 + dr;
                int ci = (ck * 683) >> 11;     // ck/3
                int kh = ck - ci * 3;
                int hh = h + kh - 1;
                float v = 0.f;
                if ((unsigned)hh < 64u && wok)
                    v = xb[ci * 4096 + hh * 64 + ww];
                slabf[(c * 48 + ck) * 36 + b] = v;
            }
        }
    }
    __syncthreads();

    // -------- roles: warp = (kq4, oh2); lane = (kg2, bg4, og4) --------
    const int kq = wid >> 1;
    const int oh = wid & 1;
    const int og = lane & 3;
    const int bg = (lane >> 2) & 3;            // b = bg*8 + jp*2 + pair
    const int kg = lane >> 4;

    const float* wm = wsf + (oh * 8 + og * 2) * 292;   // + {0,144,292,436} per m, + p

    int parity = 0;
    #pragma unroll
    for (int l = 0; l < 2; ++l) {
        const int loc = loc0 + l;

        float bv[4] = {0.f, 0.f, 0.f, 0.f};
        if (kq == 0) {
            const float* bp = bias + (size_t)loc * 32 + oh * 16 + og * 4;
            bv[0] = bp[0]; bv[1] = bp[1]; bv[2] = bp[2]; bv[3] = bp[3];
        }

        {   // wait this loc's weights
            unsigned done;
            do {
                asm volatile("{ .reg .pred p; mbarrier.try_wait.parity.shared.b64 p, [%1], %2; "
                             "selp.b32 %0, 1, 0, p; }"
                             : "=r"(done) : "r"(mb), "r"(parity) : "memory");
            } while (!done);
        }
        parity ^= 1;

        // -------- compute: 6 i-steps x 3 kw; tile 4pairs x 4o --------
        u64 acc[16];                           // [jp*4 + m]
        #pragma unroll
        for (int j = 0; j < 16; ++j) acc[j] = 0ull;

        #pragma unroll 2
        for (int i = 0; i < 6; ++i) {
            const int ck = kq * 12 + 2 * i + kg;
            const float* xr0 = slabf + (l * 48 + ck) * 36 + bg * 8;
            const float* wp  = wm + 3 * ck;
            #pragma unroll
            for (int kw = 0; kw < 3; ++kw) {
                const float* xr = xr0 + kw * 1728;          // (+48 rows)*36
                ulonglong2 Xa = *(const ulonglong2*)(xr);
                ulonglong2 Xb = *(const ulonglong2*)(xr + 4);
                #pragma unroll
                for (int m = 0; m < 4; ++m) {
                    float wv = wp[kw + (m >> 1) * 292 + (m & 1) * 144];
                    u64 wu = pack2(wv);
                    fma2(acc[m],      Xa.x, wu);
                    fma2(acc[4 + m],  Xa.y, wu);
                    fma2(acc[8 + m],  Xb.x, wu);
                    fma2(acc[12 + m], Xb.y, wu);
                }
            }
        }

        // in-warp kg reduction
        #pragma unroll
        for (int j = 0; j < 16; ++j)
            acc[j] = add2(acc[j], __shfl_xor_sync(0xffffffffu, acc[j], 16));

        __syncthreads();                       // w buf reads done

        // -------- kq reduction via slots in retired w buffer --------
        u64* slots = (u64*)sm;                 // 4 x 512 u64 = 16KB
        if (kq >= 2) {
            int s = oh * 2 + kq - 2;
            #pragma unroll
            for (int j = 0; j < 16; ++j)
                slots[s * 512 + j * 32 + lane] = acc[j];
        }
        __syncthreads();
        if (kq < 2) {
            int s = oh * 2 + kq;
            #pragma unroll
            for (int j = 0; j < 16; ++j)
                acc[j] = add2(acc[j], slots[s * 512 + j * 32 + lane]);
            if (kq == 1) {
                #pragma unroll
                for (int j = 0; j < 16; ++j)
                    slots[(oh * 2 + 1) * 512 + j * 32 + lane] = acc[j];
            }
        }
        __syncthreads();

        // -------- epilogue: coalesced float2 into permuted scratch --------
        if (kq == 0) {
            float* scr = g_scratch + (size_t)loc * 1024 + oh * 512 + bg * 8 + og * 2;
            #pragma unroll
            for (int jj = 0; jj < 8; ++jj) {
                int j = kg * 8 + jj;           // kg halves split the 16 outputs
                u64 s = add2(acc[j], slots[(oh * 2 + 1) * 512 + j * 32 + lane]);
                float lo, hi;
                unpackf2(s, lo, hi);
                float bvm = bv[j & 3];
                *(float2*)(scr + j * 32) = make_float2(lo + bvm, hi + bvm);
            }
        }
        __syncthreads();                       // slots consumed

        // -------- DMA weights for loc1 --------
        if (l == 0) {
            asm volatile("fence.proxy.async.shared::cta;" ::: "memory");
            if (tid < 32) {
                asm volatile("mbarrier.arrive.expect_tx.shared.b64 _, [%0], %1;"
                             :: "r"(mb), "r"(576) : "memory");
                const char* src = (const char*)weights + ((size_t)(loc0 + 1) * 32 + tid) * 576;
                unsigned dst = smbase + (tid >> 1) * 1168 + (tid & 1) * 576;
                asm volatile("cp.async.bulk.shared::cta.global.mbarrier::complete_tx::bytes "
                             "[%0], [%1], %2, [%3];"
                             :: "r"(dst), "l"(src), "r"(576), "r"(mb) : "memory");
            }
        }
    }
}

// un-permute + transpose, 4 tiles per CTA with all LDGs issued upfront
__global__ __launch_bounds__(256) void xonv_transpose(float* __restrict__ out)
{
    __shared__ float tile[4][32 * 33];
    const int lane = threadIdx.x & 31;
    const int wid  = threadIdx.x >> 5;

    float v[16];
    #pragma unroll
    for (int k = 0; k < 4; ++k) {              // gather: MLP 16
        int tl   = blockIdx.x * 4 + k;
        int loc0 = (tl & 127) * 32;
        int s0   = (tl >> 7) * 32;
        #pragma unroll
        for (int i = 0; i < 4; ++i) {
            int r = wid * 4 + i;
            v[k * 4 + i] = g_scratch[(size_t)(loc0 + r) * 1024 + s0 + lane];
        }
    }
    #pragma unroll
    for (int k = 0; k < 4; ++k)
        #pragma unroll
        for (int i = 0; i < 4; ++i)
            tile[k][lane * 33 + wid * 4 + i] = v[k * 4 + i];
    __syncthreads();

    #pragma unroll
    for (int k = 0; k < 4; ++k) {
        int tl   = blockIdx.x * 4 + k;
        int loc0 = (tl & 127) * 32;
        int s0   = (tl >> 7) * 32;
        #pragma unroll
        for (int i = 0; i < 4; ++i) {
            int sy = wid * 4 + i;
            int s  = s0 + sy;
            int pair = s & 1;
            int og   = (s >> 1) & 3;
            int bg   = (s >> 3) & 3;
            int j    = (s >> 5) & 15;
            int ohh  = (s >> 9) & 1;
            int b = bg * 8 + (j >> 2) * 2 + pair;
            int o = ohh * 16 + og * 4 + (j & 3);
            out[(size_t)(b * 32 + o) * 4096 + loc0 + lane] = tile[k][sy * 33 + lane];
        }
    }
}

extern "C" void kernel_launch(void* const* d_in, const int* in_sizes, int n_in,
                              void* d_out, int out_size) {
    const float* x       = (const float*)d_in[0];
    const float* weights = (const float*)d_in[1];
    const float* bias    = (const float*)d_in[2];
    float* out = (float*)d_out;
    (void)in_sizes; (void)n_in; (void)out_size;

    cudaFuncSetAttribute(xonv_main, cudaFuncAttributeMaxDynamicSharedMemorySize, SMEM_B);
    xonv_main<<<GRID, THREADS, SMEM_B>>>(x, weights, bias);
    xonv_transpose<<<1024, 256>>>(out);
}

// round 16
// speedup vs baseline: 1.9638x; 1.9638x over previous
#include <cuda_runtime.h>

typedef unsigned long long u64;

#define THREADS 256
#define GRID    2048

// ---- smem (bytes) ----
#define WBUF_B   18688          // paired o-rows: w(o,p) = (o>>1)*292 + (o&1)*144 + p (floats)
#define SLAB_OFF 18688          // slab: 192 rows (ck*4+col) x 36 floats
#define SLAB_B   27648
#define MB_OFF   (SLAB_OFF + SLAB_B)    // 46336
#define SMEM_B   (MB_OFF + 16)          // 46352 -> 4 CTAs/SM

// 16MB staging: scratch[loc][s], s = oh*512 + j*64 + bg*8 + og*2 + pair
__device__ float g_scratch[4096 * 1024];

__device__ __forceinline__ void fma2(u64& d, u64 a, u64 b) {
    asm("fma.rn.f32x2 %0, %1, %2, %0;" : "+l"(d) : "l"(a), "l"(b));
}
__device__ __forceinline__ u64 add2(u64 a, u64 b) {
    u64 r; asm("add.rn.f32x2 %0, %1, %2;" : "=l"(r) : "l"(a), "l"(b)); return r;
}
__device__ __forceinline__ u64 pack2(float v) {
    u64 r; asm("mov.b64 %0, {%1, %1};" : "=l"(r) : "f"(v)); return r;
}
__device__ __forceinline__ void unpackf2(u64 d, float& lo, float& hi) {
    asm("mov.b64 {%0, %1}, %2;" : "=f"(lo), "=f"(hi) : "l"(d));
}
__device__ __forceinline__ unsigned smem_u32(const void* p) {
    unsigned a;
    asm("{ .reg .u64 t; cvta.to.shared.u64 t, %1; cvt.u32.u64 %0, t; }" : "=r"(a) : "l"(p));
    return a;
}

__global__ __launch_bounds__(THREADS, 4) void xonv_main(
    const float* __restrict__ x,        // (32, 16, 64, 64)
    const float* __restrict__ weights,  // (64, 64, 32, 16, 3, 3)
    const float* __restrict__ bias)     // (64, 64, 32)
{
    extern __shared__ __align__(16) char sm[];
    float* wsf   = (float*)sm;
    float* slabf = (float*)(sm + SLAB_OFF);
    const unsigned smbase = smem_u32(sm);
    const unsigned mb = smbase + MB_OFF;

    const int tid  = threadIdx.x;
    const int lane = tid & 31;
    const int wid  = tid >> 5;
    const int h    = blockIdx.x >> 5;
    const int w0   = (blockIdx.x & 31) * 2;
    const int loc0 = h * 64 + w0;

    if (tid == 0)
        asm volatile("mbarrier.init.shared.b64 [%0], %1;" :: "r"(mb), "r"(32) : "memory");
    __syncthreads();

    // -------- DMA weights for loc0 --------
    if (tid < 32) {
        asm volatile("mbarrier.arrive.expect_tx.shared.b64 _, [%0], %1;"
                     :: "r"(mb), "r"(576) : "memory");
        const char* src = (const char*)weights + ((size_t)loc0 * 32 + tid) * 576;
        unsigned dst = smbase + (tid >> 1) * 1168 + (tid & 1) * 576;
        asm volatile("cp.async.bulk.shared::cta.global.mbarrier::complete_tx::bytes "
                     "[%0], [%1], %2, [%3];"
                     :: "r"(dst), "l"(src), "r"(576), "r"(mb) : "memory");
    }

    // -------- stage shared x slab: rows (ck, col 0..3), cols = w0-1..w0+2 --------
    {
        const int dr = lane >> 2;
        const int c  = lane & 3;
        const int ww = w0 + c - 1;
        const bool wok = (unsigned)ww < 64u;
        #pragma unroll
        for (int itb = 0; itb < 4; ++itb) {
            const int b = itb * 8 + wid;
            const float* xb = x + (size_t)b * 65536;
            #pragma unroll
            for (int itc = 0; itc < 6; ++itc) {
                int ck = itc * 8 + dr;
                int ci = (ck * 683) >> 11;     // ck/3
                int kh = ck - ci * 3;
                int hh = h + kh - 1;
                float v = 0.f;
                if ((unsigned)hh < 64u && wok)
                    v = xb[ci * 4096 + hh * 64 + ww];
                slabf[(ck * 4 + c) * 36 + b] = v;
            }
        }
    }
    __syncthreads();

    const int kq = wid >> 1;                   // K quarter
    const int oh = wid & 1;                    // o half
    const int bg = lane >> 2;                  // b base = bg*4
    const int og = lane & 3;                   // o = oh*16 + m*4 + og

    const float* wpf = wsf + (oh * 8 + (og >> 1)) * 292 + (og & 1) * 144 + kq * 36;

    int parity = 0;
    #pragma unroll
    for (int l = 0; l < 2; ++l) {
        const int loc = loc0 + l;

        float bv0 = 0.f, bv1 = 0.f, bv2 = 0.f, bv3 = 0.f;
        if (kq == 0) {
            const float* bp = bias + (size_t)loc * 32 + oh * 16 + og;
            bv0 = bp[0]; bv1 = bp[4]; bv2 = bp[8]; bv3 = bp[12];
        }

        {   // wait this loc's weights
            unsigned done;
            do {
                asm volatile("{ .reg .pred p; mbarrier.try_wait.parity.shared.b64 p, [%1], %2; "
                             "selp.b32 %0, 1, 0, p; }"
                             : "=r"(done) : "r"(mb), "r"(parity) : "memory");
            } while (!done);
        }
        parity ^= 1;

        // -------- compute: 12 ck per quarter, tile 4b x 4o, b-paired f32x2 --------
        u64 acc[8];                            // j = jbp*4 + m
        #pragma unroll
        for (int j = 0; j < 8; ++j) acc[j] = 0ull;

        #pragma unroll 4
        for (int cl = 0; cl < 12; ++cl) {
            const float* xr = slabf + ((kq * 12 + cl) * 4 + l) * 36 + bg * 4;
            ulonglong2 X0 = *(const ulonglong2*)(xr);
            ulonglong2 X1 = *(const ulonglong2*)(xr + 36);
            ulonglong2 X2 = *(const ulonglong2*)(xr + 72);
            const float* wp = wpf + cl * 3;
            #pragma unroll
            for (int m = 0; m < 4; ++m) {
                float wa  = wp[m * 584];
                float wb_ = wp[m * 584 + 1];
                float wc  = wp[m * 584 + 2];
                u64 wau = pack2(wa), wbu = pack2(wb_), wcu = pack2(wc);
                fma2(acc[m],     X0.x, wau); fma2(acc[4 + m], X0.y, wau);
                fma2(acc[m],     X1.x, wbu); fma2(acc[4 + m], X1.y, wbu);
                fma2(acc[m],     X2.x, wcu); fma2(acc[4 + m], X2.y, wcu);
            }
        }
        __syncthreads();                       // w buf reads done

        // -------- kq reduction via slots in retired w buffer --------
        u64* slots = (u64*)sm;                 // 4 x 256 u64
        if (kq >= 2) {
            int s = oh * 2 + kq - 2;
            #pragma unroll
            for (int j = 0; j < 8; ++j)
                slots[s * 256 + j * 32 + lane] = acc[j];
        }
        __syncthreads();
        if (kq < 2) {
            int s = oh * 2 + kq;
            #pragma unroll
            for (int j = 0; j < 8; ++j)
                acc[j] = add2(acc[j], slots[s * 256 + j * 32 + lane]);
            if (kq == 1) {
                #pragma unroll
                for (int j = 0; j < 8; ++j)
                    slots[(oh * 2 + 1) * 256 + j * 32 + lane] = acc[j];
            }
        }
        __syncthreads();

        // -------- epilogue: coalesced float2 into permuted scratch --------
        if (kq == 0) {
            float* scr = g_scratch + (size_t)loc * 1024 + oh * 512 + bg * 8 + og * 2;
            #pragma unroll
            for (int j = 0; j < 8; ++j) {
                u64 s = add2(acc[j], slots[(oh * 2 + 1) * 256 + j * 32 + lane]);
                float lo, hi;
                unpackf2(s, lo, hi);
                int m = j & 3;
                float bv = (m == 0) ? bv0 : (m == 1) ? bv1 : (m == 2) ? bv2 : bv3;
                *(float2*)(scr + j * 64) = make_float2(lo + bv, hi + bv);
            }
        }
        __syncthreads();                       // slots consumed

        // -------- DMA weights for loc1 --------
        if (l == 0) {
            asm volatile("fence.proxy.async.shared::cta;" ::: "memory");
            if (tid < 32) {
                asm volatile("mbarrier.arrive.expect_tx.shared.b64 _, [%0], %1;"
                             :: "r"(mb), "r"(576) : "memory");
                const char* src = (const char*)weights + ((size_t)(loc0 + 1) * 32 + tid) * 576;
                unsigned dst = smbase + (tid >> 1) * 1168 + (tid & 1) * 576;
                asm volatile("cp.async.bulk.shared::cta.global.mbarrier::complete_tx::bytes "
                             "[%0], [%1], %2, [%3];"
                             :: "r"(dst), "l"(src), "r"(576), "r"(mb) : "memory");
            }
        }
    }
}

// un-permute + transpose: 2 tiles/CTA, float4 loads issued up-front (MLP 2)
__global__ __launch_bounds__(256) void xonv_transpose(float* __restrict__ out)
{
    __shared__ float tile[2][32 * 33];
    const int tid  = threadIdx.x;
    const int lane = tid & 31;
    const int wid  = tid >> 5;
    const int r  = tid >> 3;                   // 0..31: loc row
    const int sq = tid & 7;                    // 0..7: s quad

    // issue both tiles' LDG.128 before any store
    float4 va, vb;
    {
        int t0 = blockIdx.x * 2;
        int t1 = t0 + 1;
        va = *(const float4*)(g_scratch + (size_t)((t0 & 127) * 32 + r) * 1024
                              + (t0 >> 7) * 32 + sq * 4);
        vb = *(const float4*)(g_scratch + (size_t)((t1 & 127) * 32 + r) * 1024
                              + (t1 >> 7) * 32 + sq * 4);
    }
    // transposed scalar STS: banks (sq*4 + r) mod 32 distinct per e -> conflict-free
    tile[0][(sq * 4 + 0) * 33 + r] = va.x;
    tile[0][(sq * 4 + 1) * 33 + r] = va.y;
    tile[0][(sq * 4 + 2) * 33 + r] = va.z;
    tile[0][(sq * 4 + 3) * 33 + r] = va.w;
    tile[1][(sq * 4 + 0) * 33 + r] = vb.x;
    tile[1][(sq * 4 + 1) * 33 + r] = vb.y;
    tile[1][(sq * 4 + 2) * 33 + r] = vb.z;
    tile[1][(sq * 4 + 3) * 33 + r] = vb.w;
    __syncthreads();

    #pragma unroll
    for (int k = 0; k < 2; ++k) {
        int tl   = blockIdx.x * 2 + k;
        int loc0 = (tl & 127) * 32;
        int s0   = (tl >> 7) * 32;
        #pragma unroll
        for (int i = 0; i < 4; ++i) {
            int sy = wid * 4 + i;
            int s  = s0 + sy;
            int pair = s & 1;
            int og   = (s >> 1) & 3;
            int bg   = (s >> 3) & 7;
            int j    = (s >> 6) & 7;
            int ohh  = (s >> 9) & 1;
            int b = bg * 4 + (j >> 2) * 2 + pair;
            int o = ohh * 16 + (j & 3) * 4 + og;
            out[(size_t)(b * 32 + o) * 4096 + loc0 + lane] = tile[k][sy * 33 + lane];
        }
    }
}

extern "C" void kernel_launch(void* const* d_in, const int* in_sizes, int n_in,
                              void* d_out, int out_size) {
    const float* x       = (const float*)d_in[0];
    const float* weights = (const float*)d_in[1];
    const float* bias    = (const float*)d_in[2];
    float* out = (float*)d_out;
    (void)in_sizes; (void)n_in; (void)out_size;

    cudaFuncSetAttribute(xonv_main, cudaFuncAttributeMaxDynamicSharedMemorySize, SMEM_B);
    xonv_main<<<GRID, THREADS, SMEM_B>>>(x, weights, bias);
    xonv_transpose<<<2048, 256>>>(out);
}